// round 12
// baseline (speedup 1.0000x reference)
#include <cuda_runtime.h>
#include <cuda_fp16.h>

#define B_DIM 32
#define N_IN 1000000
#define N_OUT 500000
#define TILE_O 128
#define SOUT_STRIDE 132   // floats per b-row: = 4 mod 32, float4-aligned

// 64 MB transposed fp16 scratch: xt[i][b] -> one 64B line per input column i.
// Kept L2-resident: all other streams use evict-first hints.
__device__ __half g_xt[(size_t)N_IN * B_DIM];

// ---------------------------------------------------------------------------
// Kernel 1: transpose+convert x(32,1e6) fp32 -> xt(1e6,32) fp16.
// 32 x 128 tile per 256-thread block. __ldcs streamed reads (protect L2),
// conflict-free smem, STG.128 xt writes that stay in L2.  (unchanged)
// ---------------------------------------------------------------------------
__global__ void __launch_bounds__(256) transpose_kernel(const float* __restrict__ x) {
    __shared__ float tile[32][129];
    const int t    = threadIdx.x;
    const int col0 = blockIdx.x * 128;

    {
        const int row = t >> 5;
        const int c4  = col0 + 4 * (t & 31);
        if (c4 < N_IN) {
            #pragma unroll
            for (int r = 0; r < 32; r += 8) {
                float4 v = __ldcs(reinterpret_cast<const float4*>(
                    &x[(size_t)(row + r) * N_IN + c4]));
                tile[row + r][4 * (t & 31) + 0] = v.x;
                tile[row + r][4 * (t & 31) + 1] = v.y;
                tile[row + r][4 * (t & 31) + 2] = v.z;
                tile[row + r][4 * (t & 31) + 3] = v.w;
            }
        }
    }
    __syncthreads();

    #pragma unroll
    for (int m = 0; m < 2; m++) {
        const int e  = m * 256 + t;
        const int cc = e >> 2;     // 0..127 : row within tile (x column)
        const int q  = e & 3;      // 8-element b-chunk
        if (col0 + cc < N_IN) {
            __half2 h0 = __floats2half2_rn(tile[8 * q + 0][cc], tile[8 * q + 1][cc]);
            __half2 h1 = __floats2half2_rn(tile[8 * q + 2][cc], tile[8 * q + 3][cc]);
            __half2 h2 = __floats2half2_rn(tile[8 * q + 4][cc], tile[8 * q + 5][cc]);
            __half2 h3 = __floats2half2_rn(tile[8 * q + 6][cc], tile[8 * q + 7][cc]);
            uint4 u;
            u.x = *reinterpret_cast<unsigned*>(&h0);
            u.y = *reinterpret_cast<unsigned*>(&h1);
            u.z = *reinterpret_cast<unsigned*>(&h2);
            u.w = *reinterpret_cast<unsigned*>(&h3);
            *reinterpret_cast<uint4*>(
                &g_xt[(size_t)(col0 + cc) * B_DIM + 8 * q]) = u;   // keep in L2
        }
    }
}

// ---------------------------------------------------------------------------
// Kernel 2: gather-reduce. 256 threads (8 warps), 128 outputs per block.
// __launch_bounds__(256, 4): lifts the 32-reg cap so all SIX gather LDG.128
// (2 output-groups x 3 taps) are issued before any consumption -> MLP=6/warp.
// One LDG.128 serves 8 outputs: lane (g=l>>2, s=l&3) reads 16B = 8 halves
// (b=8s..8s+7) of output base+g. Results staged b-major with XOR swizzle;
// coalesced __stcs float4 writes.
// ---------------------------------------------------------------------------
__global__ void __launch_bounds__(256, 4) gather_kernel(const float* __restrict__ w,
                                                        const int*   __restrict__ idx,
                                                        float*       __restrict__ out) {
    __shared__ int2  s_pair[3 * TILE_O];
    __shared__ float s_out[32 * SOUT_STRIDE];

    const int tid  = threadIdx.x;
    const int warp = tid >> 5;
    const int lane = tid & 31;
    const int g    = lane >> 2;   // output group (0..7)
    const int s    = lane & 3;    // 16B chunk: b = 8s..8s+7
    const int col0 = blockIdx.x * TILE_O;

    // Stage (idx, w) pairs for the tile, coalesced + evict-first.
    #pragma unroll
    for (int m = 0; m < 2; m++) {
        const int e = m * 256 + tid;
        if (e < 3 * TILE_O) {
            const int gi = col0 * 3 + e;
            const bool v = (gi < 3 * N_OUT);
            s_pair[e] = make_int2(v ? __ldcs(&idx[gi]) : 0,
                                  v ? __float_as_int(__ldcs(&w[gi])) : 0);
        }
    }
    __syncthreads();

    // Hoist all pair reads and all 6 gather loads up front (max MLP).
    int2  p[2][3];
    #pragma unroll
    for (int it = 0; it < 2; it++) {
        const int ol = warp * 16 + it * 8 + g;
        #pragma unroll
        for (int k = 0; k < 3; k++) p[it][k] = s_pair[ol * 3 + k];
    }

    uint4 v[2][3];
    #pragma unroll
    for (int it = 0; it < 2; it++) {
        #pragma unroll
        for (int k = 0; k < 3; k++) {
            v[it][k] = *reinterpret_cast<const uint4*>(
                &g_xt[(size_t)p[it][k].x * B_DIM + 8 * s]);
        }
    }

    #pragma unroll
    for (int it = 0; it < 2; it++) {
        const int ol = warp * 16 + it * 8 + g;
        float acc[8] = {0, 0, 0, 0, 0, 0, 0, 0};
        #pragma unroll
        for (int k = 0; k < 3; k++) {
            const float wk = __int_as_float(p[it][k].y);
            const float2 f0 = __half22float2(*reinterpret_cast<const __half2*>(&v[it][k].x));
            const float2 f1 = __half22float2(*reinterpret_cast<const __half2*>(&v[it][k].y));
            const float2 f2 = __half22float2(*reinterpret_cast<const __half2*>(&v[it][k].z));
            const float2 f3 = __half22float2(*reinterpret_cast<const __half2*>(&v[it][k].w));
            acc[0] = fmaf(wk, f0.x, acc[0]);
            acc[1] = fmaf(wk, f0.y, acc[1]);
            acc[2] = fmaf(wk, f1.x, acc[2]);
            acc[3] = fmaf(wk, f1.y, acc[3]);
            acc[4] = fmaf(wk, f2.x, acc[4]);
            acc[5] = fmaf(wk, f2.y, acc[5]);
            acc[6] = fmaf(wk, f3.x, acc[6]);
            acc[7] = fmaf(wk, f3.y, acc[7]);
        }
        // b-major staging, column XOR-swizzled by 8s (16B-granular):
        // bank = 4i + g + 8*(j^s) -> all 32 lanes distinct per STS instr.
        const int colsw = ol ^ (8 * s);
        #pragma unroll
        for (int i = 0; i < 8; i++) {
            s_out[(8 * s + i) * SOUT_STRIDE + colsw] = acc[i];
        }
    }
    __syncthreads();

    // Write 32 x 128 tile: 1024 float4; conflict-free LDS.128, coalesced
    // STG.128 streamed past L2 (__stcs).
    #pragma unroll
    for (int m = 0; m < 4; m++) {
        const int f4 = m * 256 + tid;
        const int b  = f4 >> 5;
        const int c4 = (f4 & 31) * 4;
        const int oc = col0 + c4;
        if (oc < N_OUT) {
            const int cst = c4 ^ (8 * (b >> 3));   // un-swizzle (16B aligned)
            float4 vv = *reinterpret_cast<const float4*>(
                &s_out[b * SOUT_STRIDE + cst]);
            __stcs(reinterpret_cast<float4*>(&out[(size_t)b * N_OUT + oc]), vv);
        }
    }
}

// ---------------------------------------------------------------------------
extern "C" void kernel_launch(void* const* d_in, const int* in_sizes, int n_in,
                              void* d_out, int out_size) {
    const float* x   = (const float*)d_in[0];   // (32, 1e6) fp32
    const float* w   = (const float*)d_in[1];   // (5e5, 3)  fp32
    const int*   idx = (const int*)  d_in[2];   // (5e5, 3)  int32
    float*       out = (float*)d_out;           // (32, 5e5) fp32

    transpose_kernel<<<(N_IN + 127) / 128, 256>>>(x);
    gather_kernel<<<(N_OUT + TILE_O - 1) / TILE_O, 256>>>(w, idx, out);
}